// round 10
// baseline (speedup 1.0000x reference)
#include <cuda_runtime.h>

#define H 10

// Table: intervals [x_k, x_k+h), x_k = (k - GHALF)*h, h = 2^-7 (exact).
#define GHALF 1024
#define GREC  2048                  // intervals covering [-8, 8)
#define HSTEP 7.8125e-3f            // 2^-7
#define INVH  128.0f                // 2^7
#define NBUILD 16                   // builder blocks (128 records each)

// Record k: {u0, ux0, uxx0, c3 = (uxx_{k+1}-uxx_k)/h}
__device__ __align__(16) float4 g_rec[GREC + 4];

// Monotone cross-run sync (table is REBUILT every run; counters only order it).
__device__ int g_blkctr = 0;        // blocks arrived, across all runs
__device__ int g_done   = 0;        // builder blocks finished, across all runs

__device__ __forceinline__ float fast_tanh(float z) {
    float e = __expf(2.0f * z);
    return 1.0f - __fdividef(2.0f, e + 1.0f);
}

__device__ __forceinline__ unsigned smem_u32(const void* p) {
    unsigned a;
    asm("{ .reg .u64 t; cvta.to.shared.u64 t, %1; cvt.u32.u64 %0, t; }"
        : "=r"(a) : "l"(p));
    return a;
}

__device__ __forceinline__ float3 eval_net(float xv,
    const float* sW1, const float* sb1, const float* sW2, const float* sb2,
    const float* sW3, const float* sb3, const float* sW4)
{
    float a[H], d1[H], d2[H];
#pragma unroll
    for (int j = 0; j < H; j++) {
        float w = sW1[j];
        float z = fmaf(xv, w, sb1[j]);
        float t = fast_tanh(z);
        float s = fmaf(-t, t, 1.0f);
        float ap = s * w;
        a[j] = t; d1[j] = ap; d2[j] = -2.0f * t * ap * w;
    }
    float na[H], nd1[H], nd2[H];
#pragma unroll
    for (int j = 0; j < H; j++) {
        float z = sb2[j], zp = 0.0f, zpp = 0.0f;
#pragma unroll
        for (int k = 0; k < H; k++) {
            float w = sW2[k * H + j];
            z = fmaf(a[k], w, z); zp = fmaf(d1[k], w, zp); zpp = fmaf(d2[k], w, zpp);
        }
        float t = fast_tanh(z);
        float s = fmaf(-t, t, 1.0f);
        float ap = s * zp;
        na[j] = t; nd1[j] = ap; nd2[j] = fmaf(s, zpp, -2.0f * t * ap * zp);
    }
#pragma unroll
    for (int j = 0; j < H; j++) {
        float z = sb3[j], zp = 0.0f, zpp = 0.0f;
#pragma unroll
        for (int k = 0; k < H; k++) {
            float w = sW3[k * H + j];
            z = fmaf(na[k], w, z); zp = fmaf(nd1[k], w, zp); zpp = fmaf(nd2[k], w, zpp);
        }
        float t = fast_tanh(z);
        float s = fmaf(-t, t, 1.0f);
        float ap = s * zp;
        a[j] = t; d1[j] = ap; d2[j] = fmaf(s, zpp, -2.0f * t * ap * zp);
    }
    float u = 0.0f, ux = 0.0f, uxx = 0.0f;
#pragma unroll
    for (int k = 0; k < H; k++) {
        float w = sW4[k];
        u = fmaf(a[k], w, u); ux = fmaf(d1[k], w, ux); uxx = fmaf(d2[k], w, uxx);
    }
    return make_float3(u, ux, uxx);
}

__device__ __forceinline__ void interp1(const float4* __restrict__ srec, float xv,
                                        float& u, float& ux, float& uxx)
{
    float t = xv * INVH;
    int idx = __float2int_rd(t);
    idx = max(-GHALF, min(GHALF - 1, idx));
    float d = fmaf((float)(-idx), HSTEP, xv);
    float4 r = srec[idx + GHALF];
    uxx = fmaf(d, r.w, r.z);
    ux  = fmaf(d, fmaf(d, 0.5f * r.w, r.z), r.y);
    u   = fmaf(d, fmaf(d, 0.5f * fmaf(d, 0.3333333333f * r.w, r.z), r.y), r.x);
}

__device__ __forceinline__ void do_chunk(const float4* __restrict__ srec,
                                         float4 xv, float* __restrict__ out, int c)
{
    float u0, ux0, uxx0, u1, ux1, uxx1, u2, ux2, uxx2, u3, ux3, uxx3;
    interp1(srec, xv.x, u0, ux0, uxx0);
    interp1(srec, xv.y, u1, ux1, uxx1);
    interp1(srec, xv.z, u2, ux2, uxx2);
    interp1(srec, xv.w, u3, ux3, uxx3);
    float4* o = (float4*)(out + 12LL * c);
    o[0] = make_float4(u0, ux0, uxx0, u1);
    o[1] = make_float4(ux1, uxx1, u2, ux2);
    o[2] = make_float4(uxx2, u3, ux3, uxx3);
}

__global__ void __launch_bounds__(256, 4)
fused_kernel(const float* __restrict__ x,
             const float* __restrict__ W1, const float* __restrict__ b1,
             const float* __restrict__ W2, const float* __restrict__ b2,
             const float* __restrict__ W3, const float* __restrict__ b3,
             const float* __restrict__ W4,
             float* __restrict__ out, int n)
{
    extern __shared__ float4 srec[];              // GREC float4 = 32 KB
    __shared__ int s_target;

    const int tid = threadIdx.x;

    // Per-run epoch (monotone; launches are serialized, so during run k the
    // block counter spans [k*G, (k+1)*G) and this run's builders make g_done
    // reach (k+1)*NBUILD).
    if (tid == 0) {
        int e = atomicAdd(&g_blkctr, 1);
        s_target = (e / (int)gridDim.x + 1) * NBUILD;
    }

    // ---- front-batched x prefetch (independent of the table) ----
    const int nchunks = n >> 2;
    const int S = gridDim.x * blockDim.x;
    const int t0 = blockIdx.x * blockDim.x + tid;
    const float4* xin = (const float4*)x;
    const int cmax = nchunks - 1;

    int c0 = t0, c1 = t0 + S, c2 = t0 + 2 * S, c3 = t0 + 3 * S;
    int l0 = min(c0, cmax), l1 = min(c1, cmax),
        l2 = min(c2, cmax), l3 = min(c3, cmax);
    float4 v0 = xin[l0];
    float4 v1 = xin[l1];
    float4 v2 = xin[l2];
    float4 v3 = xin[l3];

    // ---- builder blocks: 128 records each, rebuilt EVERY run ----
    if (blockIdx.x < NBUILD) {
        __shared__ float sW1[H], sb1[H], sb2[H], sb3[H], sW4[H];
        __shared__ float sW2[H * H], sW3[H * H];
        __shared__ float s_uxx[130];

        if (tid < H) {
            sW1[tid] = W1[tid]; sb1[tid] = b1[tid];
            sb2[tid] = b2[tid]; sb3[tid] = b3[tid]; sW4[tid] = W4[tid];
        }
        for (int k = tid; k < H * H; k += blockDim.x) { sW2[k] = W2[k]; sW3[k] = W3[k]; }
        __syncthreads();

        int base = blockIdx.x * 128;
        float3 V = make_float3(0.f, 0.f, 0.f);
        if (tid <= 128) {
            float xn = (float)(base + tid - GHALF) * HSTEP;   // exact
            V = eval_net(xn, sW1, sb1, sW2, sb2, sW3, sb3, sW4);
            s_uxx[tid] = V.z;
        }
        __syncthreads();
        if (tid < 128) {
            float c3v = (s_uxx[tid + 1] - V.z) * INVH;
            g_rec[base + tid] = make_float4(V.x, V.y, V.z, c3v);
        }
        __threadfence();                          // publish records
        __syncthreads();
        if (tid == 0) atomicAdd(&g_done, 1);
    }

    // ---- wait for this run's table, then pull it into smem ----
    if (tid == 0) {
        while (*(volatile int*)&g_done < s_target) { }
    }
    __syncthreads();
    __threadfence();                              // acquire table writes

    {
        unsigned sbase = smem_u32(srec);
        for (int i = tid; i < GREC; i += blockDim.x) {
            unsigned dst = sbase + i * 16u;
            const float4* src = g_rec + i;
            asm volatile("cp.async.cg.shared.global [%0], [%1], 16;"
                         :: "r"(dst), "l"(src));
        }
        asm volatile("cp.async.commit_group;");
        asm volatile("cp.async.wait_group 0;" ::: "memory");
    }
    __syncthreads();

    // ---- interpolation (identical to R9) ----
    while (true) {
        do_chunk(srec, v0, out, l0);
        if (c1 <= cmax) do_chunk(srec, v1, out, l1);
        if (c2 <= cmax) do_chunk(srec, v2, out, l2);
        if (c3 <= cmax) do_chunk(srec, v3, out, l3);

        c0 += 4 * S; c1 += 4 * S; c2 += 4 * S; c3 += 4 * S;
        if (c0 > cmax) break;
        l0 = min(c0, cmax); l1 = min(c1, cmax);
        l2 = min(c2, cmax); l3 = min(c3, cmax);
        v0 = xin[l0];
        v1 = xin[l1];
        v2 = xin[l2];
        v3 = xin[l3];
    }

    // Tail n % 4 (empty for N = 2M)
    if (blockIdx.x == 0 && tid == 0) {
        for (int p = nchunks * 4; p < n; p++) {
            float u, ux, uxx;
            interp1(srec, x[p], u, ux, uxx);
            out[3 * p + 0] = u; out[3 * p + 1] = ux; out[3 * p + 2] = uxx;
        }
    }
}

extern "C" void kernel_launch(void* const* d_in, const int* in_sizes, int n_in,
                              void* d_out, int out_size) {
    const float* x  = (const float*)d_in[0];
    const float* W1 = (const float*)d_in[1];
    const float* b1 = (const float*)d_in[2];
    const float* W2 = (const float*)d_in[3];
    const float* b2 = (const float*)d_in[4];
    const float* W3 = (const float*)d_in[5];
    const float* b3 = (const float*)d_in[6];
    const float* W4 = (const float*)d_in[7];
    float* out = (float*)d_out;
    int n = in_sizes[0];

    const int smem_bytes = GREC * sizeof(float4);         // 32768
    cudaFuncSetAttribute(fused_kernel,
                         cudaFuncAttributeMaxDynamicSharedMemorySize, smem_bytes);
    int dev = 0, sms = 148;
    cudaGetDevice(&dev);
    cudaDeviceGetAttribute(&sms, cudaDevAttrMultiProcessorCount, dev);

    // grid = 4 blocks/SM: guaranteed fully resident (regs/smem/warps all fit),
    // so the in-kernel producer/consumer spin cannot deadlock.
    fused_kernel<<<sms * 4, 256, smem_bytes>>>(x, W1, b1, W2, b2, W3, b3, W4, out, n);
}

// round 11
// speedup vs baseline: 1.2937x; 1.2937x over previous
#include <cuda_runtime.h>

#define H 10

// Table: intervals [x_k, x_k+h), x_k = (k - GHALF)*h, h = 2^-7 (exact).
#define GHALF 1024
#define GREC  2048                  // intervals covering [-8, 8)
#define HSTEP 7.8125e-3f            // 2^-7
#define INVH  128.0f                // 2^7
#define BDIM  256

// Record k: {u0, ux0, uxx0, c3 = (uxx_{k+1}-uxx_k)/h}
__device__ __align__(16) float4 g_rec[GREC + 4];

__device__ __forceinline__ float fast_tanh(float z) {
    float e = __expf(2.0f * z);
    return 1.0f - __fdividef(2.0f, e + 1.0f);
}

__device__ __forceinline__ unsigned smem_u32(const void* p) {
    unsigned a;
    asm("{ .reg .u64 t; cvta.to.shared.u64 t, %1; cvt.u32.u64 %0, t; }"
        : "=r"(a) : "l"(p));
    return a;
}

__device__ __forceinline__ float3 eval_net(float xv,
    const float* sW1, const float* sb1, const float* sW2, const float* sb2,
    const float* sW3, const float* sb3, const float* sW4)
{
    float a[H], d1[H], d2[H];
#pragma unroll
    for (int j = 0; j < H; j++) {
        float w = sW1[j];
        float z = fmaf(xv, w, sb1[j]);
        float t = fast_tanh(z);
        float s = fmaf(-t, t, 1.0f);
        float ap = s * w;
        a[j] = t; d1[j] = ap; d2[j] = -2.0f * t * ap * w;
    }
    float na[H], nd1[H], nd2[H];
#pragma unroll
    for (int j = 0; j < H; j++) {
        float z = sb2[j], zp = 0.0f, zpp = 0.0f;
#pragma unroll
        for (int k = 0; k < H; k++) {
            float w = sW2[k * H + j];
            z = fmaf(a[k], w, z); zp = fmaf(d1[k], w, zp); zpp = fmaf(d2[k], w, zpp);
        }
        float t = fast_tanh(z);
        float s = fmaf(-t, t, 1.0f);
        float ap = s * zp;
        na[j] = t; nd1[j] = ap; nd2[j] = fmaf(s, zpp, -2.0f * t * ap * zp);
    }
#pragma unroll
    for (int j = 0; j < H; j++) {
        float z = sb3[j], zp = 0.0f, zpp = 0.0f;
#pragma unroll
        for (int k = 0; k < H; k++) {
            float w = sW3[k * H + j];
            z = fmaf(na[k], w, z); zp = fmaf(nd1[k], w, zp); zpp = fmaf(nd2[k], w, zpp);
        }
        float t = fast_tanh(z);
        float s = fmaf(-t, t, 1.0f);
        float ap = s * zp;
        a[j] = t; d1[j] = ap; d2[j] = fmaf(s, zpp, -2.0f * t * ap * zp);
    }
    float u = 0.0f, ux = 0.0f, uxx = 0.0f;
#pragma unroll
    for (int k = 0; k < H; k++) {
        float w = sW4[k];
        u = fmaf(a[k], w, u); ux = fmaf(d1[k], w, ux); uxx = fmaf(d2[k], w, uxx);
    }
    return make_float3(u, ux, uxx);
}

// ---------- Kernel A: 128 records/block; 129 node evals shared via smem ----------
#define BT 160
__global__ void __launch_bounds__(BT)
build_table_kernel(const float* __restrict__ W1, const float* __restrict__ b1,
                   const float* __restrict__ W2, const float* __restrict__ b2,
                   const float* __restrict__ W3, const float* __restrict__ b3,
                   const float* __restrict__ W4)
{
    __shared__ float sW1[H], sb1[H], sb2[H], sb3[H], sW4[H];
    __shared__ float sW2[H * H], sW3[H * H];
    __shared__ float s_uxx[130];

    int tid = threadIdx.x;
    if (tid < H) {
        sW1[tid] = W1[tid]; sb1[tid] = b1[tid];
        sb2[tid] = b2[tid]; sb3[tid] = b3[tid]; sW4[tid] = W4[tid];
    }
    for (int k = tid; k < H * H; k += BT) { sW2[k] = W2[k]; sW3[k] = W3[k]; }
    __syncthreads();

    int base = blockIdx.x * 128;
    float3 V = make_float3(0.f, 0.f, 0.f);
    if (tid <= 128) {
        float xn = (float)(base + tid - GHALF) * HSTEP;
        V = eval_net(xn, sW1, sb1, sW2, sb2, sW3, sb3, sW4);
        s_uxx[tid] = V.z;
    }
    __syncthreads();

    if (tid < 128) {
        float c3 = (s_uxx[tid + 1] - V.z) * INVH;
        g_rec[base + tid] = make_float4(V.x, V.y, V.z, c3);
    }
}

// ---------- Kernel B: batched gather + smem-staged coalesced stores ----------
__device__ __forceinline__ void interp1(const float4* __restrict__ srec, float xv,
                                        float& u, float& ux, float& uxx)
{
    float t = xv * INVH;
    int idx = __float2int_rd(t);
    idx = max(-GHALF, min(GHALF - 1, idx));
    float d = fmaf((float)(-idx), HSTEP, xv);
    float4 r = srec[idx + GHALF];
    uxx = fmaf(d, r.w, r.z);
    ux  = fmaf(d, fmaf(d, 0.5f * r.w, r.z), r.y);
    u   = fmaf(d, fmaf(d, 0.5f * fmaf(d, 0.3333333333f * r.w, r.z), r.y), r.x);
}

// Compute one chunk into stage, then flush the block's contiguous 256-chunk
// region with fully coalesced float4 stores.
__device__ __forceinline__ void slot_store(const float4* __restrict__ srec,
                                           float4* __restrict__ stage,
                                           float4 xv, float* __restrict__ out,
                                           int start /* uniform */, int cmax, int tid)
{
    float u0, ux0, uxx0, u1, ux1, uxx1, u2, ux2, uxx2, u3, ux3, uxx3;
    interp1(srec, xv.x, u0, ux0, uxx0);
    interp1(srec, xv.y, u1, ux1, uxx1);
    interp1(srec, xv.z, u2, ux2, uxx2);
    interp1(srec, xv.w, u3, ux3, uxx3);
    stage[tid * 3 + 0] = make_float4(u0, ux0, uxx0, u1);
    stage[tid * 3 + 1] = make_float4(ux1, uxx1, u2, ux2);
    stage[tid * 3 + 2] = make_float4(uxx2, u3, ux3, uxx3);
    __syncthreads();
    float4* o4 = (float4*)out;
    long long obase = 3LL * start;
#pragma unroll
    for (int q = tid; q < 3 * BDIM; q += BDIM) {
        int chunk = start + q / 3;
        if (chunk <= cmax) o4[obase + q] = stage[q];
    }
    __syncthreads();
}

__global__ void __launch_bounds__(BDIM, 4)
interp_kernel(const float* __restrict__ x, float* __restrict__ out, int n)
{
    extern __shared__ float4 smem[];
    float4* srec  = smem;                         // GREC = 32 KB
    float4* stage = smem + GREC;                  // 768 float4 = 12 KB

    const int tid = threadIdx.x;

    // Non-blocking table fill via cp.async.
    {
        unsigned sbase = smem_u32(srec);
        for (int i = tid; i < GREC; i += BDIM) {
            unsigned dst = sbase + i * 16u;
            const float4* src = g_rec + i;
            asm volatile("cp.async.cg.shared.global [%0], [%1], 16;"
                         :: "r"(dst), "l"(src));
        }
        asm volatile("cp.async.commit_group;");
    }

    const int nchunks = n >> 2;
    const int S = gridDim.x * BDIM;               // stride in chunks
    const int base0 = blockIdx.x * BDIM;          // uniform block base
    const int t0 = base0 + tid;
    const float4* xin = (const float4*)x;
    const int cmax = nchunks - 1;

    int c0 = t0, c1 = t0 + S, c2 = t0 + 2 * S, c3 = t0 + 3 * S;
    int b0 = base0;                               // uniform slot starts

    bool first = true;
    while (c0 <= cmax) {
        // front-batched unconditional loads (clamped -> MLP = 4)
        int l0 = min(c0, cmax), l1 = min(c1, cmax),
            l2 = min(c2, cmax), l3 = min(c3, cmax);
        float4 v0 = xin[l0];
        float4 v1 = xin[l1];
        float4 v2 = xin[l2];
        float4 v3 = xin[l3];

        if (first) {
            first = false;
            asm volatile("cp.async.wait_group 0;" ::: "memory");
            __syncthreads();
        }

        slot_store(srec, stage, v0, out, b0,         cmax, tid);
        if (b0 + S     <= cmax) slot_store(srec, stage, v1, out, b0 + S,     cmax, tid);
        if (b0 + 2 * S <= cmax) slot_store(srec, stage, v2, out, b0 + 2 * S, cmax, tid);
        if (b0 + 3 * S <= cmax) slot_store(srec, stage, v3, out, b0 + 3 * S, cmax, tid);

        c0 += 4 * S; c1 += 4 * S; c2 += 4 * S; c3 += 4 * S;
        b0 += 4 * S;
    }

    // Tail n % 4 (empty for N = 2M)
    if (blockIdx.x == 0 && tid == 0) {
        asm volatile("cp.async.wait_group 0;" ::: "memory");
        for (int p = nchunks * 4; p < n; p++) {
            float u, ux, uxx;
            interp1(srec, x[p], u, ux, uxx);
            out[3 * p + 0] = u; out[3 * p + 1] = ux; out[3 * p + 2] = uxx;
        }
    }
}

extern "C" void kernel_launch(void* const* d_in, const int* in_sizes, int n_in,
                              void* d_out, int out_size) {
    const float* x  = (const float*)d_in[0];
    const float* W1 = (const float*)d_in[1];
    const float* b1 = (const float*)d_in[2];
    const float* W2 = (const float*)d_in[3];
    const float* b2 = (const float*)d_in[4];
    const float* W3 = (const float*)d_in[5];
    const float* b3 = (const float*)d_in[6];
    const float* W4 = (const float*)d_in[7];
    float* out = (float*)d_out;
    int n = in_sizes[0];

    build_table_kernel<<<GREC / 128, BT>>>(W1, b1, W2, b2, W3, b3, W4);

    const int smem_bytes = (GREC + 3 * BDIM) * sizeof(float4);   // 32 KB + 12 KB
    cudaFuncSetAttribute(interp_kernel,
                         cudaFuncAttributeMaxDynamicSharedMemorySize, smem_bytes);
    int dev = 0, sms = 148;
    cudaGetDevice(&dev);
    cudaDeviceGetAttribute(&sms, cudaDevAttrMultiProcessorCount, dev);
    interp_kernel<<<sms * 4, BDIM, smem_bytes>>>(x, out, n);
}

// round 12
// speedup vs baseline: 1.3022x; 1.0065x over previous
#include <cuda_runtime.h>

#define H 10

// Table: intervals [x_k, x_k+h), x_k = (k - GHALF)*h, h = 2^-7 (exact).
#define GHALF 1024
#define GREC  2048                  // intervals covering [-8, 8)
#define HSTEP 7.8125e-3f            // 2^-7
#define INVH  128.0f                // 2^7
#define BDIM  256

// Record k: {u0, ux0, uxx0, c3 = (uxx_{k+1}-uxx_k)/h}
__device__ __align__(16) float4 g_rec[GREC + 4];

__device__ __forceinline__ float fast_tanh(float z) {
    float e = __expf(2.0f * z);
    return 1.0f - __fdividef(2.0f, e + 1.0f);
}

__device__ __forceinline__ unsigned smem_u32(const void* p) {
    unsigned a;
    asm("{ .reg .u64 t; cvta.to.shared.u64 t, %1; cvt.u32.u64 %0, t; }"
        : "=r"(a) : "l"(p));
    return a;
}

__device__ __forceinline__ float3 eval_net(float xv,
    const float* sW1, const float* sb1, const float* sW2, const float* sb2,
    const float* sW3, const float* sb3, const float* sW4)
{
    float a[H], d1[H], d2[H];
#pragma unroll
    for (int j = 0; j < H; j++) {
        float w = sW1[j];
        float z = fmaf(xv, w, sb1[j]);
        float t = fast_tanh(z);
        float s = fmaf(-t, t, 1.0f);
        float ap = s * w;
        a[j] = t; d1[j] = ap; d2[j] = -2.0f * t * ap * w;
    }
    float na[H], nd1[H], nd2[H];
#pragma unroll
    for (int j = 0; j < H; j++) {
        float z = sb2[j], zp = 0.0f, zpp = 0.0f;
#pragma unroll
        for (int k = 0; k < H; k++) {
            float w = sW2[k * H + j];
            z = fmaf(a[k], w, z); zp = fmaf(d1[k], w, zp); zpp = fmaf(d2[k], w, zpp);
        }
        float t = fast_tanh(z);
        float s = fmaf(-t, t, 1.0f);
        float ap = s * zp;
        na[j] = t; nd1[j] = ap; nd2[j] = fmaf(s, zpp, -2.0f * t * ap * zp);
    }
#pragma unroll
    for (int j = 0; j < H; j++) {
        float z = sb3[j], zp = 0.0f, zpp = 0.0f;
#pragma unroll
        for (int k = 0; k < H; k++) {
            float w = sW3[k * H + j];
            z = fmaf(na[k], w, z); zp = fmaf(nd1[k], w, zp); zpp = fmaf(nd2[k], w, zpp);
        }
        float t = fast_tanh(z);
        float s = fmaf(-t, t, 1.0f);
        float ap = s * zp;
        a[j] = t; d1[j] = ap; d2[j] = fmaf(s, zpp, -2.0f * t * ap * zp);
    }
    float u = 0.0f, ux = 0.0f, uxx = 0.0f;
#pragma unroll
    for (int k = 0; k < H; k++) {
        float w = sW4[k];
        u = fmaf(a[k], w, u); ux = fmaf(d1[k], w, ux); uxx = fmaf(d2[k], w, uxx);
    }
    return make_float3(u, ux, uxx);
}

// ---------- Kernel A: 128 records/block ----------
#define BT 160
__global__ void __launch_bounds__(BT)
build_table_kernel(const float* __restrict__ W1, const float* __restrict__ b1,
                   const float* __restrict__ W2, const float* __restrict__ b2,
                   const float* __restrict__ W3, const float* __restrict__ b3,
                   const float* __restrict__ W4)
{
    // Let the dependent interp kernel launch immediately (PDL).
    cudaTriggerProgrammaticLaunchCompletion();

    __shared__ float sW1[H], sb1[H], sb2[H], sb3[H], sW4[H];
    __shared__ float sW2[H * H], sW3[H * H];
    __shared__ float s_uxx[130];

    int tid = threadIdx.x;
    if (tid < H) {
        sW1[tid] = W1[tid]; sb1[tid] = b1[tid];
        sb2[tid] = b2[tid]; sb3[tid] = b3[tid]; sW4[tid] = W4[tid];
    }
    for (int k = tid; k < H * H; k += BT) { sW2[k] = W2[k]; sW3[k] = W3[k]; }
    __syncthreads();

    int base = blockIdx.x * 128;
    float3 V = make_float3(0.f, 0.f, 0.f);
    if (tid <= 128) {
        float xn = (float)(base + tid - GHALF) * HSTEP;
        V = eval_net(xn, sW1, sb1, sW2, sb2, sW3, sb3, sW4);
        s_uxx[tid] = V.z;
    }
    __syncthreads();

    if (tid < 128) {
        float c3 = (s_uxx[tid + 1] - V.z) * INVH;
        g_rec[base + tid] = make_float4(V.x, V.y, V.z, c3);
    }
}

// ---------- Kernel B ----------
__device__ __forceinline__ void interp1(const float4* __restrict__ srec, float xv,
                                        float& u, float& ux, float& uxx)
{
    float t = xv * INVH;
    int idx = __float2int_rd(t);
    idx = max(-GHALF, min(GHALF - 1, idx));
    float d = fmaf((float)(-idx), HSTEP, xv);
    float4 r = srec[idx + GHALF];
    uxx = fmaf(d, r.w, r.z);
    ux  = fmaf(d, fmaf(d, 0.5f * r.w, r.z), r.y);
    u   = fmaf(d, fmaf(d, 0.5f * fmaf(d, 0.3333333333f * r.w, r.z), r.y), r.x);
}

// Compute one slot into a stage buffer, single barrier, coalesced flush.
// Double-buffered stages: caller alternates; one barrier per slot is safe
// because any STS to stage P happens after the barrier of the slot that
// flushed P (all flush LDS of P complete before that barrier is passed... 
// precisely: each thread does flush(P) before arriving at the NEXT slot's
// barrier, so by the time stage P is reused two slots later, its flush is done).
__device__ __forceinline__ void slot_store(const float4* __restrict__ srec,
                                           float4* __restrict__ stage,
                                           float4 xv, float* __restrict__ out,
                                           int start /* uniform */, int cmax, int tid)
{
    float u0, ux0, uxx0, u1, ux1, uxx1, u2, ux2, uxx2, u3, ux3, uxx3;
    interp1(srec, xv.x, u0, ux0, uxx0);
    interp1(srec, xv.y, u1, ux1, uxx1);
    interp1(srec, xv.z, u2, ux2, uxx2);
    interp1(srec, xv.w, u3, ux3, uxx3);
    stage[tid * 3 + 0] = make_float4(u0, ux0, uxx0, u1);
    stage[tid * 3 + 1] = make_float4(ux1, uxx1, u2, ux2);
    stage[tid * 3 + 2] = make_float4(uxx2, u3, ux3, uxx3);
    __syncthreads();
    float4* o4 = (float4*)out;
    long long obase = 3LL * start;
#pragma unroll
    for (int q = tid; q < 3 * BDIM; q += BDIM) {
        int chunk = start + q / 3;
        if (chunk <= cmax) o4[obase + q] = stage[q];
    }
}

__global__ void __launch_bounds__(BDIM, 4)
interp_kernel(const float* __restrict__ x, float* __restrict__ out, int n)
{
    extern __shared__ float4 smem[];
    float4* srec   = smem;                        // GREC = 32 KB
    float4* stageA = smem + GREC;                 // 12 KB
    float4* stageB = stageA + 3 * BDIM;           // 12 KB

    const int tid = threadIdx.x;
    const int nchunks = n >> 2;
    const int S = gridDim.x * BDIM;
    const int base0 = blockIdx.x * BDIM;
    const int t0 = base0 + tid;
    const float4* xin = (const float4*)x;
    const int cmax = nchunks - 1;

    // Front-issue the first 4 x loads BEFORE waiting on the build kernel:
    // their DRAM latency overlaps the producer's tail (PDL).
    int c0 = t0, c1 = t0 + S, c2 = t0 + 2 * S, c3 = t0 + 3 * S;
    int l0 = min(c0, cmax), l1 = min(c1, cmax),
        l2 = min(c2, cmax), l3 = min(c3, cmax);
    float4 v0 = xin[l0];
    float4 v1 = xin[l1];
    float4 v2 = xin[l2];
    float4 v3 = xin[l3];

    // Wait for build_table_kernel to fully complete, then pull the table.
    cudaGridDependencySynchronize();
    {
        unsigned sbase = smem_u32(srec);
        for (int i = tid; i < GREC; i += BDIM) {
            unsigned dst = sbase + i * 16u;
            const float4* src = g_rec + i;
            asm volatile("cp.async.cg.shared.global [%0], [%1], 16;"
                         :: "r"(dst), "l"(src));
        }
        asm volatile("cp.async.commit_group;");
        asm volatile("cp.async.wait_group 0;" ::: "memory");
    }
    __syncthreads();

    int b0 = base0;
    while (c0 <= cmax) {
        slot_store(srec, stageA, v0, out, b0, cmax, tid);
        if (b0 + S <= cmax)     slot_store(srec, stageB, v1, out, b0 + S,     cmax, tid);
        if (b0 + 2 * S <= cmax) slot_store(srec, stageA, v2, out, b0 + 2 * S, cmax, tid);
        if (b0 + 3 * S <= cmax) slot_store(srec, stageB, v3, out, b0 + 3 * S, cmax, tid);

        c0 += 4 * S; c1 += 4 * S; c2 += 4 * S; c3 += 4 * S;
        b0 += 4 * S;
        if (c0 > cmax) break;
        // barrier inside the last slot_store separates these STS-free loads;
        // stage reuse is protected by the per-slot barriers (see comment above)
        l0 = min(c0, cmax); l1 = min(c1, cmax);
        l2 = min(c2, cmax); l3 = min(c3, cmax);
        v0 = xin[l0];
        v1 = xin[l1];
        v2 = xin[l2];
        v3 = xin[l3];
        __syncthreads();   // ensure last flush of stageA completed before overwrite
    }

    // Tail n % 4 (empty for N = 2M)
    if (blockIdx.x == 0 && tid == 0) {
        for (int p = nchunks * 4; p < n; p++) {
            float u, ux, uxx;
            interp1(srec, x[p], u, ux, uxx);
            out[3 * p + 0] = u; out[3 * p + 1] = ux; out[3 * p + 2] = uxx;
        }
    }
}

extern "C" void kernel_launch(void* const* d_in, const int* in_sizes, int n_in,
                              void* d_out, int out_size) {
    const float* x  = (const float*)d_in[0];
    const float* W1 = (const float*)d_in[1];
    const float* b1 = (const float*)d_in[2];
    const float* W2 = (const float*)d_in[3];
    const float* b2 = (const float*)d_in[4];
    const float* W3 = (const float*)d_in[5];
    const float* b3 = (const float*)d_in[6];
    const float* W4 = (const float*)d_in[7];
    float* out = (float*)d_out;
    int n = in_sizes[0];

    build_table_kernel<<<GREC / 128, BT>>>(W1, b1, W2, b2, W3, b3, W4);

    const int smem_bytes = (GREC + 6 * BDIM) * sizeof(float4);   // 32 + 24 KB
    static bool attr_set = false;
    if (!attr_set) {
        cudaFuncSetAttribute(interp_kernel,
                             cudaFuncAttributeMaxDynamicSharedMemorySize, smem_bytes);
        attr_set = true;
    }
    int dev = 0, sms = 148;
    cudaGetDevice(&dev);
    cudaDeviceGetAttribute(&sms, cudaDevAttrMultiProcessorCount, dev);

    // PDL: interp launches while build is still running; interp gates on
    // cudaGridDependencySynchronize() before reading the table.
    cudaLaunchConfig_t cfg = {};
    cfg.gridDim = dim3(sms * 4, 1, 1);
    cfg.blockDim = dim3(BDIM, 1, 1);
    cfg.dynamicSmemBytes = smem_bytes;
    cfg.stream = 0;
    cudaLaunchAttribute attrs[1];
    attrs[0].id = cudaLaunchAttributeProgrammaticStreamSerialization;
    attrs[0].val.programmaticStreamSerializationAllowed = 1;
    cfg.attrs = attrs;
    cfg.numAttrs = 1;
    cudaLaunchKernelEx(&cfg, interp_kernel, x, out, n);
}